// round 12
// baseline (speedup 1.0000x reference)
#include <cuda_runtime.h>
#include <cuda_bf16.h>
#include <stdint.h>

#define NN   50000
#define NE   800000
#define FIN  128
#define DIM  256
#define NG   512
#define NL   3
#define OUTD (NL*DIM)   // 768
#define BN_EPS 1e-5f
#define MPAD 50048      // 391*128, padded row count for GEMM tiles

// Scratch
__device__ float4 g_bufB4[NN*DIM/4];      // m (post-MLP, f32)
__device__ uint4  g_aggH4[MPAD*DIM*2/16]; // agg hi (bf16 [MPAD][K])
__device__ uint4  g_aggL4[MPAD*DIM*2/16];
__device__ uint4  g_tH4[MPAD*DIM*2/16];   // t hi (bf16 [MPAD][256])
__device__ uint4  g_tL4[MPAD*DIM*2/16];
__device__ float  g_stats[2*DIM];         // per-column sum, sumsq
__device__ float  g_sc[DIM], g_sh[DIM];   // published BN affine of prev layer
__device__ int    g_idx64;
// Pre-split bf16 weight images, N-major ([n][k]) per (t,chunk) 128x32 tile.
__device__ __nv_bfloat16 g_whi[360448];
__device__ __nv_bfloat16 g_wlo[360448];
// CSR scratch
__device__ int g_deg[NN];
__device__ int g_rowstart[NN];
__device__ int g_pos[NE];
__device__ int g_src32[NE];
__device__ int g_dst32[NE];
__device__ int g_eidx[NE];

// ---------------------------------------------------------------------------
__device__ __forceinline__ uint32_t smem_u32(const void* p) {
    uint32_t a;
    asm("{ .reg .u64 t; cvta.to.shared.u64 t, %1; cvt.u32.u64 %0, t; }" : "=r"(a) : "l"(p));
    return a;
}
__device__ __forceinline__ uint32_t pack_bf2(float a, float b) {
    uint32_t r;
    asm("cvt.rn.bf16x2.f32 %0, %1, %2;" : "=r"(r) : "f"(b), "f"(a));
    return r;
}
__device__ __forceinline__ void splitbf(float x, float& h, float& l) {
    __nv_bfloat16 hb = __float2bfloat16_rn(x);
    h = __bfloat162float(hb);
    l = x - h;
}
#define LDSM_X4(r0, r1, r2, r3, addr)                                          \
    asm volatile("ldmatrix.sync.aligned.m8n8.x4.shared.b16 {%0,%1,%2,%3}, [%4];" \
                 : "=r"(r0), "=r"(r1), "=r"(r2), "=r"(r3) : "r"(addr))
#define MMA_BF16(c, a0, a1, a2, a3, b0, b1)                                    \
    asm volatile(                                                              \
        "mma.sync.aligned.m16n8k16.row.col.f32.bf16.bf16.f32 "                 \
        "{%0,%1,%2,%3}, {%4,%5,%6,%7}, {%8,%9}, {%0,%1,%2,%3};"                \
        : "+f"(c[0]), "+f"(c[1]), "+f"(c[2]), "+f"(c[3])                       \
        : "r"(a0), "r"(a1), "r"(a2), "r"(a3), "r"(b0), "r"(b1))
#define CP_ASYNC16(dst, src)                                                   \
    asm volatile("cp.async.ca.shared.global [%0], [%1], 16;"                   \
                 :: "r"(dst), "l"(src) : "memory")
#define CP_COMMIT() asm volatile("cp.async.commit_group;" ::: "memory")

__device__ __forceinline__ long long load_idx(const void* p, long long i, int is64) {
    return is64 ? ((const long long*)p)[i] : (long long)((const int*)p)[i];
}

// ---------------------------------------------------------------------------
__global__ void zeroall_kernel(float* pooled, const unsigned int* ei_raw) {
    int i = blockIdx.x * blockDim.x + threadIdx.x;
    if (i < NG * OUTD) pooled[i] = 0.f;
    if (i < NN) g_deg[i] = 0;
    if (i == 0) {
        unsigned int z = 0u;
#pragma unroll
        for (int k = 0; k < 32; k++) z |= ei_raw[2*k + 1];
        g_idx64 = (z == 0u) ? 1 : 0;
    }
}

__global__ void zero_kernel(float* p, int n) {
    int i = blockIdx.x * blockDim.x + threadIdx.x;
    if (i < n) p[i] = 0.f;
}

// ---------------------------------------------------------------------------
#define WTOT 360448
__global__ void prep_kernel(const void* __restrict__ ei,
                            const float* w0, const float* w1, const float* w2,
                            const float* w3, const float* w4, const float* w5,
                            __nv_bfloat16* __restrict__ whi,
                            __nv_bfloat16* __restrict__ wlo) {
    int stride = gridDim.x * blockDim.x;
    int gidx = blockIdx.x * blockDim.x + threadIdx.x;
    int is64 = g_idx64;
    for (int e = gidx; e < NE; e += stride) {
        int s = (int)load_idx(ei, e, is64);
        int d = (int)load_idx(ei, (long long)NE + e, is64);
        g_src32[e] = s;
        g_dst32[e] = d;
        g_pos[e] = atomicAdd(&g_deg[d], 1);
    }
    const float* ws[6] = {w0, w1, w2, w3, w4, w5};
    const int woffs[6] = {0, 32768, 98304, 163840, 229376, 294912};
    for (int idx = gidx; idx < WTOT; idx += stride) {
        int wsel, local, K;
        if (idx < 32768) { wsel = 0; local = idx; K = FIN; }
        else { wsel = 1 + ((idx - 32768) >> 16); local = (idx - 32768) & 65535; K = DIM; }
        int k = local >> 8, n = local & 255;
        int nch = K >> 5;
        int t = n >> 7, nl = n & 127, c = k >> 5, kk = k & 31;
        int off = woffs[wsel] + (t * nch + c) * 4096 + nl * 32 + kk;
        float x = ws[wsel][local];
        float h, l;
        splitbf(x, h, l);
        whi[off] = __float2bfloat16_rn(h);
        wlo[off] = __float2bfloat16_rn(l);
    }
}

__global__ void scan_kernel() {
    __shared__ int sm[1024];
    int t = threadIdx.x;
    const int CH = (NN + 1023) / 1024;
    int b0 = t * CH, b1 = min(b0 + CH, NN);
    int s = 0;
    for (int i = b0; i < b1; i++) s += g_deg[i];
    sm[t] = s;
    __syncthreads();
    for (int off = 1; off < 1024; off <<= 1) {
        int v = (t >= off) ? sm[t - off] : 0;
        __syncthreads();
        sm[t] += v;
        __syncthreads();
    }
    int run = (t == 0) ? 0 : sm[t - 1];
    for (int i = b0; i < b1; i++) { g_rowstart[i] = run; run += g_deg[i]; }
}

__global__ void fillcsr_kernel() {
    int stride = gridDim.x * blockDim.x;
    for (int e = blockIdx.x * blockDim.x + threadIdx.x; e < NE; e += stride)
        g_eidx[g_rowstart[g_dst32[e]] + g_pos[e]] = g_src32[e];
}

// ---------------------------------------------------------------------------
// CSR gather + (optional) BN affine + bf16 hi/lo split:
// out = split( sc ⊙ (h_i + Σ_{j->i} h_j) + (deg+1)·sh )   [affine if use_affine]
// One warp per node.
__global__ void gather_split(const float* __restrict__ h, int F, int use_affine,
                             __nv_bfloat16* __restrict__ oH,
                             __nv_bfloat16* __restrict__ oL) {
    int gw = (blockIdx.x * blockDim.x + threadIdx.x) >> 5;
    if (gw >= NN) return;
    int lane = threadIdx.x & 31;
    int start = g_rowstart[gw], deg = g_deg[gw];
    int F4 = F >> 2;
    bool wide = (F4 == 64);
    const float4* hv = (const float4*)h;
    const float4* hp = hv + (long long)gw * F4 + lane;
    float4 a0 = hp[0];
    float4 a1 = wide ? hp[32] : make_float4(0.f, 0.f, 0.f, 0.f);
    for (int i0 = 0; i0 < deg; i0 += 32) {
        int mye = (i0 + lane < deg) ? g_eidx[start + i0 + lane] : 0;
        int cnt = min(32, deg - i0);
        for (int j = 0; j < cnt; j++) {
            int s = __shfl_sync(0xffffffffu, mye, j);
            const float4* sp = hv + (long long)s * F4 + lane;
            float4 v = sp[0];
            a0.x += v.x; a0.y += v.y; a0.z += v.z; a0.w += v.w;
            if (wide) {
                float4 u = sp[32];
                a1.x += u.x; a1.y += u.y; a1.z += u.z; a1.w += u.w;
            }
        }
    }
    int c0 = lane * 4;
    if (use_affine) {
        float cnt = (float)(deg + 1);
        a0.x = g_sc[c0+0]*a0.x + cnt*g_sh[c0+0];
        a0.y = g_sc[c0+1]*a0.y + cnt*g_sh[c0+1];
        a0.z = g_sc[c0+2]*a0.z + cnt*g_sh[c0+2];
        a0.w = g_sc[c0+3]*a0.w + cnt*g_sh[c0+3];
        if (wide) {
            int c1 = 128 + c0;
            a1.x = g_sc[c1+0]*a1.x + cnt*g_sh[c1+0];
            a1.y = g_sc[c1+1]*a1.y + cnt*g_sh[c1+1];
            a1.z = g_sc[c1+2]*a1.z + cnt*g_sh[c1+2];
            a1.w = g_sc[c1+3]*a1.w + cnt*g_sh[c1+3];
        }
    }
    // split & write (hi/lo bf16, 8B per vec)
    {
        float h0,l0,h1,l1,h2,l2,h3,l3;
        splitbf(a0.x,h0,l0); splitbf(a0.y,h1,l1); splitbf(a0.z,h2,l2); splitbf(a0.w,h3,l3);
        uint2 H; H.x = pack_bf2(h0,h1); H.y = pack_bf2(h2,h3);
        uint2 L; L.x = pack_bf2(l0,l1); L.y = pack_bf2(l2,l3);
        *(uint2*)(oH + (size_t)gw * F + c0) = H;
        *(uint2*)(oL + (size_t)gw * F + c0) = L;
    }
    if (wide) {
        float h0,l0,h1,l1,h2,l2,h3,l3;
        splitbf(a1.x,h0,l0); splitbf(a1.y,h1,l1); splitbf(a1.z,h2,l2); splitbf(a1.w,h3,l3);
        uint2 H; H.x = pack_bf2(h0,h1); H.y = pack_bf2(h2,h3);
        uint2 L; L.x = pack_bf2(l0,l1); L.y = pack_bf2(l2,l3);
        *(uint2*)(oH + (size_t)gw * F + 128 + c0) = H;
        *(uint2*)(oL + (size_t)gw * F + 128 + c0) = L;
    }
}

// ---------------------------------------------------------------------------
// 3xBF16 tensor-core GEMM, full-N, pre-split A: C = relu(A@W + bias).
// A and B both arrive as pre-split bf16 hi/lo images via cp.async — the
// mainloop has ZERO conversion arithmetic.
// mode 0: write C as bf16 hi/lo (for next GEMM); mode 1: f32 C + BN stats.
#define ARS 80
#define AL_OFF 10240
#define BH_OFF 20480
#define BL_OFF 40960
#define STG    61440

__global__ void __launch_bounds__(512) bf16x3_gemm(
    const uint4* __restrict__ AH, const uint4* __restrict__ AL,
    const __nv_bfloat16* __restrict__ Whi, const __nv_bfloat16* __restrict__ Wlo,
    const float* __restrict__ bias,
    __nv_bfloat16* __restrict__ CH, __nv_bfloat16* __restrict__ CL,
    float* __restrict__ Cf,
    int M, int K, int mode) {
    extern __shared__ __align__(16) char dsm[];
    int tid = threadIdx.x, wid = tid >> 5, lane = tid & 31;
    int bm = blockIdx.x;
    int nch = K >> 5;

    uint32_t sb = (smem_u32(dsm) + 127) & ~127u;
    int m_off = (wid & 3) * 32;
    int n_off = (wid >> 2) * 64;

    int aRowL = (lane & 7) + ((lane >> 3) & 1) * 8;
    int aColL = (lane >> 4) * 16;
    int bRowL = ((lane >> 4) * 8) + (lane & 7);
    int bColL = ((lane >> 3) & 1) * 16;

    float acc[2][8][4] = {};

    // A cp.async indexing: thread -> (row, seg); 512 = 128 rows x 4 segs
    int rowA = tid >> 2, segA = tid & 3;
    long long aRowBase = ((long long)(bm * 128 + rowA) * K) >> 3;  // uint4 units
    uint32_t aDst = rowA * ARS + segA * 16;

    auto issueAB = [&](int c, uint32_t stg) {
        long long aIdx = aRowBase + c * 4 + segA;
        CP_ASYNC16(stg + aDst, AH + aIdx);
        CP_ASYNC16(stg + aDst + AL_OFF, AL + aIdx);
#pragma unroll
        for (int i = 0; i < 2; i++) {
            int p = tid + i * 512;
            int row = p >> 2, seg = p & 3;
            int t = row >> 7, nl = row & 127;
            long long srcIdx = ((long long)(t * nch + c) * 512) + nl * 4 + seg;
            uint32_t dst = stg + BH_OFF + row * ARS + seg * 16;
            CP_ASYNC16(dst, (const uint4*)Whi + srcIdx);
            CP_ASYNC16(dst + (BL_OFF - BH_OFF), (const uint4*)Wlo + srcIdx);
        }
    };

    issueAB(0, sb);
    CP_COMMIT();

    for (int c = 0; c < nch; c++) {
        uint32_t stg = sb + (c & 1) * STG;
        if (c + 1 < nch) {
            issueAB(c + 1, sb + ((c + 1) & 1) * STG);
            CP_COMMIT();
            asm volatile("cp.async.wait_group 1;" ::: "memory");
        } else {
            asm volatile("cp.async.wait_group 0;" ::: "memory");
        }
        __syncthreads();

#pragma unroll
        for (int ks = 0; ks < 2; ks++) {
            uint32_t aH[2][4], aL[2][4];
#pragma unroll
            for (int mt = 0; mt < 2; mt++) {
                uint32_t ad = stg + (m_off + mt * 16 + aRowL) * ARS + ks * 32 + aColL;
                LDSM_X4(aH[mt][0], aH[mt][1], aH[mt][2], aH[mt][3], ad);
                LDSM_X4(aL[mt][0], aL[mt][1], aL[mt][2], aL[mt][3], ad + AL_OFF);
            }
#pragma unroll
            for (int p = 0; p < 4; p++) {
                uint32_t bH[2][2], bL[2][2];
                uint32_t ad = stg + BH_OFF + (n_off + p * 16 + bRowL) * ARS + ks * 32 + bColL;
                LDSM_X4(bH[0][0], bH[0][1], bH[1][0], bH[1][1], ad);
                LDSM_X4(bL[0][0], bL[0][1], bL[1][0], bL[1][1], ad + (BL_OFF - BH_OFF));
#pragma unroll
                for (int mt = 0; mt < 2; mt++)
#pragma unroll
                    for (int q = 0; q < 2; q++)
                        MMA_BF16(acc[mt][2*p+q], aH[mt][0], aH[mt][1], aH[mt][2], aH[mt][3],
                                 bH[q][0], bH[q][1]);
#pragma unroll
                for (int mt = 0; mt < 2; mt++)
#pragma unroll
                    for (int q = 0; q < 2; q++)
                        MMA_BF16(acc[mt][2*p+q], aL[mt][0], aL[mt][1], aL[mt][2], aL[mt][3],
                                 bH[q][0], bH[q][1]);
#pragma unroll
                for (int mt = 0; mt < 2; mt++)
#pragma unroll
                    for (int q = 0; q < 2; q++)
                        MMA_BF16(acc[mt][2*p+q], aH[mt][0], aH[mt][1], aH[mt][2], aH[mt][3],
                                 bL[q][0], bL[q][1]);
            }
        }
        __syncthreads();
    }

    // ---- epilogue ----
    int gid = lane >> 2, tig = lane & 3;
    if (mode == 0) {
        // bias + relu + split to bf16 hi/lo (for next GEMM's A)
#pragma unroll
        for (int nt = 0; nt < 8; nt++) {
            int col = n_off + nt * 8 + tig * 2;
            float b0 = bias[col], b1 = bias[col + 1];
#pragma unroll
            for (int mt = 0; mt < 2; mt++) {
                int r0 = bm * 128 + m_off + mt * 16 + gid;
                float* cc = acc[mt][nt];
                if (r0 < M) {
                    float o0 = fmaxf(cc[0] + b0, 0.f);
                    float o1 = fmaxf(cc[1] + b1, 0.f);
                    float h0,l0,h1,l1;
                    splitbf(o0,h0,l0); splitbf(o1,h1,l1);
                    *(uint32_t*)(CH + (size_t)r0 * 256 + col) = pack_bf2(h0,h1);
                    *(uint32_t*)(CL + (size_t)r0 * 256 + col) = pack_bf2(l0,l1);
                }
                if (r0 + 8 < M) {
                    float o2 = fmaxf(cc[2] + b0, 0.f);
                    float o3 = fmaxf(cc[3] + b1, 0.f);
                    float h2,l2,h3,l3;
                    splitbf(o2,h2,l2); splitbf(o3,h3,l3);
                    *(uint32_t*)(CH + (size_t)(r0+8) * 256 + col) = pack_bf2(h2,h3);
                    *(uint32_t*)(CL + (size_t)(r0+8) * 256 + col) = pack_bf2(l2,l3);
                }
            }
        }
    } else {
        // bias + relu, f32 out + fused BN stats
#pragma unroll
        for (int nt = 0; nt < 8; nt++) {
            int col = n_off + nt * 8 + tig * 2;
            float b0 = bias[col], b1 = bias[col + 1];
            float s0 = 0.f, s1 = 0.f, q0 = 0.f, q1 = 0.f;
#pragma unroll
            for (int mt = 0; mt < 2; mt++) {
                int r0 = bm * 128 + m_off + mt * 16 + gid;
                float* cc = acc[mt][nt];
                if (r0 < M) {
                    float o0 = fmaxf(cc[0] + b0, 0.f);
                    float o1 = fmaxf(cc[1] + b1, 0.f);
                    float2 o; o.x = o0; o.y = o1;
                    *(float2*)(Cf + (long long)r0 * 256 + col) = o;
                    s0 += o0; s1 += o1; q0 += o0 * o0; q1 += o1 * o1;
                }
                if (r0 + 8 < M) {
                    float o2 = fmaxf(cc[2] + b0, 0.f);
                    float o3 = fmaxf(cc[3] + b1, 0.f);
                    float2 o; o.x = o2; o.y = o3;
                    *(float2*)(Cf + (long long)(r0 + 8) * 256 + col) = o;
                    s0 += o2; s1 += o3; q0 += o2 * o2; q1 += o3 * o3;
                }
            }
#pragma unroll
            for (int m = 4; m < 32; m <<= 1) {
                s0 += __shfl_xor_sync(0xffffffffu, s0, m);
                s1 += __shfl_xor_sync(0xffffffffu, s1, m);
                q0 += __shfl_xor_sync(0xffffffffu, q0, m);
                q1 += __shfl_xor_sync(0xffffffffu, q1, m);
            }
            if (gid == 0) {
                atomicAdd(&g_stats[col], s0);
                atomicAdd(&g_stats[col + 1], s1);
                atomicAdd(&g_stats[DIM + col], q0);
                atomicAdd(&g_stats[DIM + col + 1], q1);
            }
        }
    }
}

// ---------------------------------------------------------------------------
// Per-layer output: norm(m) -> outn slice + pooled sums (sorted-batch runs).
// Block 0 publishes the affine (g_sc/g_sh) for the next layer's gather.
#define ROWS_PB 128
__global__ void outpool_kernel(const float* __restrict__ m,
                               const float* __restrict__ g, const float* __restrict__ b,
                               const void* __restrict__ batch,
                               float* __restrict__ outn,
                               float* __restrict__ pooled, int layer) {
    int col = threadIdx.x;
    int is64 = g_idx64;
    float mu  = g_stats[col] * (1.f / NN);
    float var = g_stats[DIM + col] * (1.f / NN) - mu * mu;
    float sc  = g[col] * rsqrtf(var + BN_EPS);
    float sh  = b[col] - mu * sc;
    if (blockIdx.x == 0) { g_sc[col] = sc; g_sh[col] = sh; }

    int n0 = blockIdx.x * ROWS_PB;
    int n1 = min(n0 + ROWS_PB, NN);
    float acc = 0.f;
    long long cur = load_idx(batch, n0, is64);
    for (int n = n0; n < n1; n++) {
        float v = m[(long long)n * DIM + col] * sc + sh;
        outn[(long long)n * OUTD + layer * DIM + col] = v;
        long long bb = load_idx(batch, n, is64);
        if (bb != cur) {
            atomicAdd(&pooled[cur * OUTD + layer * DIM + col], acc);
            acc = 0.f;
            cur = bb;
        }
        acc += v;
    }
    atomicAdd(&pooled[cur * OUTD + layer * DIM + col], acc);
}

// ---------------------------------------------------------------------------
extern "C" void kernel_launch(void* const* d_in, const int* in_sizes, int n_in,
                              void* d_out, int out_size) {
    const float* x     = (const float*)d_in[0];
    const void*  ei    = d_in[1];
    const void*  batch = d_in[2];

    float* out    = (float*)d_out;
    float* pooled = out;                          // [NG, OUTD]
    float* outn   = out + (long long)NG * OUTD;   // [NN, OUTD]

    float *bufB, *stats;
    __nv_bfloat16 *whi, *wlo;
    uint4 *aggH, *aggL, *tH, *tL;
    cudaGetSymbolAddress((void**)&bufB, g_bufB4);
    cudaGetSymbolAddress((void**)&stats, g_stats);
    cudaGetSymbolAddress((void**)&whi, g_whi);
    cudaGetSymbolAddress((void**)&wlo, g_wlo);
    cudaGetSymbolAddress((void**)&aggH, g_aggH4);
    cudaGetSymbolAddress((void**)&aggL, g_aggL4);
    cudaGetSymbolAddress((void**)&tH, g_tH4);
    cudaGetSymbolAddress((void**)&tL, g_tL4);

    const int DSMEM = 2 * STG + 256;   // 123136
    cudaFuncSetAttribute(bf16x3_gemm, cudaFuncAttributeMaxDynamicSharedMemorySize, DSMEM);

    // setup: zeros + dtype detect, edge/weight prep, CSR build
    zeroall_kernel<<<1536, 256>>>(pooled, (const unsigned int*)ei);
    prep_kernel<<<3125, 256>>>(ei,
        (const float*)d_in[3],  (const float*)d_in[5],
        (const float*)d_in[9],  (const float*)d_in[11],
        (const float*)d_in[15], (const float*)d_in[17],
        whi, wlo);
    scan_kernel<<<1, 1024>>>();
    fillcsr_kernel<<<3125, 256>>>();

    const int woffs[6] = {0, 32768, 98304, 163840, 229376, 294912};

    const float* h = x;
    for (int l = 0; l < NL; l++) {
        int F = (l == 0) ? FIN : DIM;
        const float* b1 = (const float*)d_in[3 + 6 * l + 1];
        const float* b2 = (const float*)d_in[3 + 6 * l + 3];
        const float* gg = (const float*)d_in[3 + 6 * l + 4];
        const float* bb = (const float*)d_in[3 + 6 * l + 5];

        // gather (+ prev-layer BN affine) -> pre-split bf16 agg
        gather_split<<<6250, 256>>>(h, F, l > 0,
                                    (__nv_bfloat16*)aggH, (__nv_bfloat16*)aggL);

        int grid = (NN + 127) / 128;
        // GEMM1: agg -> t (bf16 hi/lo)
        bf16x3_gemm<<<grid, 512, DSMEM>>>(aggH, aggL,
            whi + woffs[2*l], wlo + woffs[2*l], b1,
            (__nv_bfloat16*)tH, (__nv_bfloat16*)tL, nullptr, NN, F, 0);
        zero_kernel<<<2, 256>>>(stats, 2 * DIM);
        // GEMM2: t -> m (f32) + BN stats
        bf16x3_gemm<<<grid, 512, DSMEM>>>(tH, tL,
            whi + woffs[2*l+1], wlo + woffs[2*l+1], b2,
            nullptr, nullptr, bufB, NN, DIM, 1);

        // outputs: outn slice + pooled; publish affine for next gather
        outpool_kernel<<<(NN + ROWS_PB - 1) / ROWS_PB, DIM>>>(
            bufB, gg, bb, batch, outn, pooled, l);

        h = bufB;
    }
}

// round 13
// speedup vs baseline: 1.0434x; 1.0434x over previous
#include <cuda_runtime.h>
#include <cuda_bf16.h>
#include <stdint.h>

#define NN   50000
#define NE   800000
#define FIN  128
#define DIM  256
#define NG   512
#define NL   3
#define OUTD (NL*DIM)   // 768
#define BN_EPS 1e-5f
#define MPAD 50048      // 391*128

// Scratch
__device__ float4 g_bufB4[NN*DIM/4];      // m (post-MLP, f32)
__device__ uint4  g_aggH4[MPAD*DIM*2/16]; // agg hi (bf16 [MPAD][K])
__device__ uint4  g_aggL4[MPAD*DIM*2/16];
__device__ float  g_stats[2*DIM];         // per-column sum, sumsq
__device__ float  g_sc[DIM], g_sh[DIM];   // published BN affine of prev layer
__device__ int    g_idx64;
// Pre-split bf16 weight images, N-major ([n][k]) per (t,chunk) 128x32 tile.
__device__ __nv_bfloat16 g_whi[360448];
__device__ __nv_bfloat16 g_wlo[360448];
// CSR scratch
__device__ int g_deg[NN];
__device__ int g_rowstart[NN + 1];
__device__ int g_pos[NE];
__device__ int g_src32[NE];
__device__ int g_dst32[NE];
__device__ int g_eidx[NE];

// ---------------------------------------------------------------------------
__device__ __forceinline__ uint32_t smem_u32(const void* p) {
    uint32_t a;
    asm("{ .reg .u64 t; cvta.to.shared.u64 t, %1; cvt.u32.u64 %0, t; }" : "=r"(a) : "l"(p));
    return a;
}
__device__ __forceinline__ uint32_t pack_bf2(float a, float b) {
    uint32_t r;
    asm("cvt.rn.bf16x2.f32 %0, %1, %2;" : "=r"(r) : "f"(b), "f"(a));
    return r;
}
__device__ __forceinline__ void splitbf(float x, float& h, float& l) {
    __nv_bfloat16 hb = __float2bfloat16_rn(x);
    h = __bfloat162float(hb);
    l = x - h;
}
#define LDSM_X4(r0, r1, r2, r3, addr)                                          \
    asm volatile("ldmatrix.sync.aligned.m8n8.x4.shared.b16 {%0,%1,%2,%3}, [%4];" \
                 : "=r"(r0), "=r"(r1), "=r"(r2), "=r"(r3) : "r"(addr))
#define MMA_BF16(c, a0, a1, a2, a3, b0, b1)                                    \
    asm volatile(                                                              \
        "mma.sync.aligned.m16n8k16.row.col.f32.bf16.bf16.f32 "                 \
        "{%0,%1,%2,%3}, {%4,%5,%6,%7}, {%8,%9}, {%0,%1,%2,%3};"                \
        : "+f"(c[0]), "+f"(c[1]), "+f"(c[2]), "+f"(c[3])                       \
        : "r"(a0), "r"(a1), "r"(a2), "r"(a3), "r"(b0), "r"(b1))
#define CP_ASYNC16(dst, src)                                                   \
    asm volatile("cp.async.ca.shared.global [%0], [%1], 16;"                   \
                 :: "r"(dst), "l"(src) : "memory")
#define CP_COMMIT() asm volatile("cp.async.commit_group;" ::: "memory")

__device__ __forceinline__ long long load_idx(const void* p, long long i, int is64) {
    return is64 ? ((const long long*)p)[i] : (long long)((const int*)p)[i];
}

// ---------------------------------------------------------------------------
// prep: per-thread dtype detect, edge decode + degree histogram, weight
// hi/lo split images, pooled zeroing. (g_deg is zeroed by scan each call.)
#define WTOT 360448
__global__ void prep_kernel(const void* __restrict__ ei,
                            const float* w0, const float* w1, const float* w2,
                            const float* w3, const float* w4, const float* w5,
                            __nv_bfloat16* __restrict__ whi,
                            __nv_bfloat16* __restrict__ wlo,
                            float* __restrict__ pooled) {
    int stride = gridDim.x * blockDim.x;
    int gidx = blockIdx.x * blockDim.x + threadIdx.x;
    // local dtype detect: 8 odd 32-bit words all zero <=> int64 indices
    unsigned int z = 0u;
    const unsigned int* er = (const unsigned int*)ei;
#pragma unroll
    for (int k = 0; k < 8; k++) z |= er[2 * k + 1];
    int is64 = (z == 0u) ? 1 : 0;
    if (gidx == 0) g_idx64 = is64;

    if (gidx < NG * OUTD) pooled[gidx] = 0.f;

    for (int e = gidx; e < NE; e += stride) {
        int s = (int)load_idx(ei, e, is64);
        int d = (int)load_idx(ei, (long long)NE + e, is64);
        g_src32[e] = s;
        g_dst32[e] = d;
        g_pos[e] = atomicAdd(&g_deg[d], 1);
    }
    const float* ws[6] = {w0, w1, w2, w3, w4, w5};
    const int woffs[6] = {0, 32768, 98304, 163840, 229376, 294912};
    for (int idx = gidx; idx < WTOT; idx += stride) {
        int wsel, local, K;
        if (idx < 32768) { wsel = 0; local = idx; K = FIN; }
        else { wsel = 1 + ((idx - 32768) >> 16); local = (idx - 32768) & 65535; K = DIM; }
        int k = local >> 8, n = local & 255;
        int nch = K >> 5;
        int t = n >> 7, nl = n & 127, c = k >> 5, kk = k & 31;
        int off = woffs[wsel] + (t * nch + c) * 4096 + nl * 32 + kk;
        float x = ws[wsel][local];
        float h, l;
        splitbf(x, h, l);
        whi[off] = __float2bfloat16_rn(h);
        wlo[off] = __float2bfloat16_rn(l);
    }
}

// Single-block scan: degrees -> rowstart (+ sentinel), then re-zero degrees.
__global__ void scan_kernel() {
    __shared__ int sm[1024];
    int t = threadIdx.x;
    const int CH = (NN + 1023) / 1024;
    int b0 = t * CH, b1 = min(b0 + CH, NN);
    int s = 0;
    for (int i = b0; i < b1; i++) s += g_deg[i];
    sm[t] = s;
    __syncthreads();
    for (int off = 1; off < 1024; off <<= 1) {
        int v = (t >= off) ? sm[t - off] : 0;
        __syncthreads();
        sm[t] += v;
        __syncthreads();
    }
    int run = (t == 0) ? 0 : sm[t - 1];
    for (int i = b0; i < b1; i++) { g_rowstart[i] = run; run += g_deg[i]; }
    if (t == 1023) g_rowstart[NN] = sm[1023];
    // re-zero degrees for the NEXT call's histogram (deterministic state)
    for (int i = b0; i < b1; i++) g_deg[i] = 0;
}

__global__ void fillcsr_kernel() {
    int stride = gridDim.x * blockDim.x;
    for (int e = blockIdx.x * blockDim.x + threadIdx.x; e < NE; e += stride)
        g_eidx[g_rowstart[g_dst32[e]] + g_pos[e]] = g_src32[e];
}

// ---------------------------------------------------------------------------
// CSR gather + (optional) prev BN affine + bf16 hi/lo split. One warp/node.
// Blocks 0-1 also zero g_stats for this layer's fused-stats GEMM.
__global__ void gather_split(const float* __restrict__ h, int F, int use_affine,
                             __nv_bfloat16* __restrict__ oH,
                             __nv_bfloat16* __restrict__ oL) {
    if (blockIdx.x < 2) {
        int i = blockIdx.x * 256 + threadIdx.x;
        if (i < 2 * DIM) g_stats[i] = 0.f;
    }
    int gw = (blockIdx.x * blockDim.x + threadIdx.x) >> 5;
    if (gw >= NN) return;
    int lane = threadIdx.x & 31;
    int start = g_rowstart[gw];
    int deg = g_rowstart[gw + 1] - start;
    int F4 = F >> 2;
    bool wide = (F4 == 64);
    const float4* hv = (const float4*)h;
    const float4* hp = hv + (long long)gw * F4 + lane;
    float4 a0 = hp[0];
    float4 a1 = wide ? hp[32] : make_float4(0.f, 0.f, 0.f, 0.f);
    for (int i0 = 0; i0 < deg; i0 += 32) {
        int mye = (i0 + lane < deg) ? g_eidx[start + i0 + lane] : 0;
        int cnt = min(32, deg - i0);
        for (int j = 0; j < cnt; j++) {
            int s = __shfl_sync(0xffffffffu, mye, j);
            const float4* sp = hv + (long long)s * F4 + lane;
            float4 v = sp[0];
            a0.x += v.x; a0.y += v.y; a0.z += v.z; a0.w += v.w;
            if (wide) {
                float4 u = sp[32];
                a1.x += u.x; a1.y += u.y; a1.z += u.z; a1.w += u.w;
            }
        }
    }
    int c0 = lane * 4;
    if (use_affine) {
        float cnt = (float)(deg + 1);
        a0.x = g_sc[c0+0]*a0.x + cnt*g_sh[c0+0];
        a0.y = g_sc[c0+1]*a0.y + cnt*g_sh[c0+1];
        a0.z = g_sc[c0+2]*a0.z + cnt*g_sh[c0+2];
        a0.w = g_sc[c0+3]*a0.w + cnt*g_sh[c0+3];
        if (wide) {
            int c1 = 128 + c0;
            a1.x = g_sc[c1+0]*a1.x + cnt*g_sh[c1+0];
            a1.y = g_sc[c1+1]*a1.y + cnt*g_sh[c1+1];
            a1.z = g_sc[c1+2]*a1.z + cnt*g_sh[c1+2];
            a1.w = g_sc[c1+3]*a1.w + cnt*g_sh[c1+3];
        }
    }
    {
        float h0,l0,h1,l1,h2,l2,h3,l3;
        splitbf(a0.x,h0,l0); splitbf(a0.y,h1,l1); splitbf(a0.z,h2,l2); splitbf(a0.w,h3,l3);
        uint2 H; H.x = pack_bf2(h0,h1); H.y = pack_bf2(h2,h3);
        uint2 L; L.x = pack_bf2(l0,l1); L.y = pack_bf2(l2,l3);
        *(uint2*)(oH + (size_t)gw * F + c0) = H;
        *(uint2*)(oL + (size_t)gw * F + c0) = L;
    }
    if (wide) {
        float h0,l0,h1,l1,h2,l2,h3,l3;
        splitbf(a1.x,h0,l0); splitbf(a1.y,h1,l1); splitbf(a1.z,h2,l2); splitbf(a1.w,h3,l3);
        uint2 H; H.x = pack_bf2(h0,h1); H.y = pack_bf2(h2,h3);
        uint2 L; L.x = pack_bf2(l0,l1); L.y = pack_bf2(l2,l3);
        *(uint2*)(oH + (size_t)gw * F + 128 + c0) = H;
        *(uint2*)(oL + (size_t)gw * F + 128 + c0) = L;
    }
}

// ---------------------------------------------------------------------------
// Fused MLP: m = relu(relu(agg@W1+b1)@W2+b2), t kept entirely in SMEM.
// 512 threads, 128-row x 256-col tiles, 3xBF16 compensated MMA, fused BN stats.
// SMEM map: buf0 [0,61440): A_hi/A_lo/B_hi/B_lo stage; t region [61440,196608)
//           doubles as phase-1 stage buf1 (t written only after mainloop).
#define ARS 80
#define AL_OFF 10240
#define BH_OFF 20480
#define BL_OFF 40960
#define STG1   61440
#define T_HI   61440
#define T_LO   129024
#define TSTR   528
#define MLP_SMEM 196608

__global__ void __launch_bounds__(512) mlp_fused(
    const uint4* __restrict__ AH, const uint4* __restrict__ AL,
    const __nv_bfloat16* __restrict__ W1h, const __nv_bfloat16* __restrict__ W1l,
    const float* __restrict__ b1,
    const __nv_bfloat16* __restrict__ W2h, const __nv_bfloat16* __restrict__ W2l,
    const float* __restrict__ b2,
    float* __restrict__ Cf, int M, int K1) {
    extern __shared__ __align__(16) char dsm[];
    int tid = threadIdx.x, wid = tid >> 5, lane = tid & 31;
    int bm = blockIdx.x;
    int nch1 = K1 >> 5;

    uint32_t sb = (smem_u32(dsm) + 127) & ~127u;
    int m_off = (wid & 3) * 32;
    int n_off = (wid >> 2) * 64;

    int aRowL = (lane & 7) + ((lane >> 3) & 1) * 8;
    int aColL = (lane >> 4) * 16;
    int bRowL = ((lane >> 4) * 8) + (lane & 7);
    int bColL = ((lane >> 3) & 1) * 16;
    int gid = lane >> 2, tig = lane & 3;

    float acc[2][8][4] = {};

    int rowA = tid >> 2, segA = tid & 3;
    long long aRowBase = ((long long)(bm * 128 + rowA) * K1) >> 3;
    uint32_t aDst = rowA * ARS + segA * 16;

    auto issue1 = [&](int c, uint32_t stg) {
        long long aIdx = aRowBase + c * 4 + segA;
        CP_ASYNC16(stg + aDst, AH + aIdx);
        CP_ASYNC16(stg + aDst + AL_OFF, AL + aIdx);
#pragma unroll
        for (int i = 0; i < 2; i++) {
            int p = tid + i * 512;
            int row = p >> 2, seg = p & 3;
            int t = row >> 7, nl = row & 127;
            long long srcIdx = ((long long)(t * nch1 + c) * 512) + nl * 4 + seg;
            uint32_t dst = stg + BH_OFF + row * ARS + seg * 16;
            CP_ASYNC16(dst, (const uint4*)W1h + srcIdx);
            CP_ASYNC16(dst + (BL_OFF - BH_OFF), (const uint4*)W1l + srcIdx);
        }
    };

    // ===== phase 1: t = relu(agg @ W1 + b1), double-buffered =====
    issue1(0, sb);
    CP_COMMIT();
    for (int c = 0; c < nch1; c++) {
        uint32_t stg = sb + (c & 1) * STG1;
        if (c + 1 < nch1) {
            issue1(c + 1, sb + ((c + 1) & 1) * STG1);
            CP_COMMIT();
            asm volatile("cp.async.wait_group 1;" ::: "memory");
        } else {
            asm volatile("cp.async.wait_group 0;" ::: "memory");
        }
        __syncthreads();
#pragma unroll
        for (int ks = 0; ks < 2; ks++) {
            uint32_t aH[2][4], aL[2][4];
#pragma unroll
            for (int mt = 0; mt < 2; mt++) {
                uint32_t ad = stg + (m_off + mt * 16 + aRowL) * ARS + ks * 32 + aColL;
                LDSM_X4(aH[mt][0], aH[mt][1], aH[mt][2], aH[mt][3], ad);
                LDSM_X4(aL[mt][0], aL[mt][1], aL[mt][2], aL[mt][3], ad + AL_OFF);
            }
#pragma unroll
            for (int p = 0; p < 4; p++) {
                uint32_t bH[2][2], bL[2][2];
                uint32_t ad = stg + BH_OFF + (n_off + p * 16 + bRowL) * ARS + ks * 32 + bColL;
                LDSM_X4(bH[0][0], bH[0][1], bH[1][0], bH[1][1], ad);
                LDSM_X4(bL[0][0], bL[0][1], bL[1][0], bL[1][1], ad + (BL_OFF - BH_OFF));
#pragma unroll
                for (int mt = 0; mt < 2; mt++)
#pragma unroll
                    for (int q = 0; q < 2; q++)
                        MMA_BF16(acc[mt][2*p+q], aH[mt][0], aH[mt][1], aH[mt][2], aH[mt][3],
                                 bH[q][0], bH[q][1]);
#pragma unroll
                for (int mt = 0; mt < 2; mt++)
#pragma unroll
                    for (int q = 0; q < 2; q++)
                        MMA_BF16(acc[mt][2*p+q], aL[mt][0], aL[mt][1], aL[mt][2], aL[mt][3],
                                 bH[q][0], bH[q][1]);
#pragma unroll
                for (int mt = 0; mt < 2; mt++)
#pragma unroll
                    for (int q = 0; q < 2; q++)
                        MMA_BF16(acc[mt][2*p+q], aH[mt][0], aH[mt][1], aH[mt][2], aH[mt][3],
                                 bL[q][0], bL[q][1]);
            }
        }
        __syncthreads();
    }

    // ===== phase-1 epilogue: bias+relu+split -> t in SMEM; reset acc =====
#pragma unroll
    for (int nt = 0; nt < 8; nt++) {
        int col = n_off + nt * 8 + tig * 2;
        float c0 = b1[col], c1 = b1[col + 1];
#pragma unroll
        for (int mt = 0; mt < 2; mt++) {
            float* cc = acc[mt][nt];
            int r0 = m_off + mt * 16 + gid;
            {
                float o0 = fmaxf(cc[0] + c0, 0.f);
                float o1 = fmaxf(cc[1] + c1, 0.f);
                float h0,l0,h1,l1;
                splitbf(o0,h0,l0); splitbf(o1,h1,l1);
                uint32_t ad = sb + T_HI + r0 * TSTR + col * 2;
                asm volatile("st.shared.b32 [%0], %1;" :: "r"(ad), "r"(pack_bf2(h0,h1)) : "memory");
                asm volatile("st.shared.b32 [%0], %1;" :: "r"(ad + (T_LO - T_HI)), "r"(pack_bf2(l0,l1)) : "memory");
            }
            {
                float o2 = fmaxf(cc[2] + c0, 0.f);
                float o3 = fmaxf(cc[3] + c1, 0.f);
                float h2,l2,h3,l3;
                splitbf(o2,h2,l2); splitbf(o3,h3,l3);
                uint32_t ad = sb + T_HI + (r0 + 8) * TSTR + col * 2;
                asm volatile("st.shared.b32 [%0], %1;" :: "r"(ad), "r"(pack_bf2(h2,h3)) : "memory");
                asm volatile("st.shared.b32 [%0], %1;" :: "r"(ad + (T_LO - T_HI)), "r"(pack_bf2(l2,l3)) : "memory");
            }
            cc[0] = cc[1] = cc[2] = cc[3] = 0.f;
        }
    }
    __syncthreads();

    // ===== phase 2: m = relu(t @ W2 + b2), A from SMEM t, B single-buffered =====
    for (int c = 0; c < 8; c++) {
#pragma unroll
        for (int i = 0; i < 2; i++) {
            int p = tid + i * 512;
            int row = p >> 2, seg = p & 3;
            int t = row >> 7, nl = row & 127;
            long long srcIdx = ((long long)(t * 8 + c) * 512) + nl * 4 + seg;
            uint32_t dst = sb + BH_OFF + row * ARS + seg * 16;
            CP_ASYNC16(dst, (const uint4*)W2h + srcIdx);
            CP_ASYNC16(dst + (BL_OFF - BH_OFF), (const uint4*)W2l + srcIdx);
        }
        CP_COMMIT();
        asm volatile("cp.async.wait_group 0;" ::: "memory");
        __syncthreads();
#pragma unroll
        for (int ks = 0; ks < 2; ks++) {
            uint32_t aH[2][4], aL[2][4];
#pragma unroll
            for (int mt = 0; mt < 2; mt++) {
                uint32_t ad = sb + T_HI + (m_off + mt * 16 + aRowL) * TSTR + c * 64 + ks * 32 + aColL;
                LDSM_X4(aH[mt][0], aH[mt][1], aH[mt][2], aH[mt][3], ad);
                LDSM_X4(aL[mt][0], aL[mt][1], aL[mt][2], aL[mt][3], ad + (T_LO - T_HI));
            }
#pragma unroll
            for (int p = 0; p < 4; p++) {
                uint32_t bH[2][2], bL[2][2];
                uint32_t ad = sb + BH_OFF + (n_off + p * 16 + bRowL) * ARS + ks * 32 + bColL;
                LDSM_X4(bH[0][0], bH[0][1], bH[1][0], bH[1][1], ad);
                LDSM_X4(bL[0][0], bL[0][1], bL[1][0], bL[1][1], ad + (BL_OFF - BH_OFF));
#pragma unroll
                for (int mt = 0; mt < 2; mt++)
#pragma unroll
                    for (int q = 0; q < 2; q++)
                        MMA_BF16(acc[mt][2*p+q], aH[mt][0], aH[mt][1], aH[mt][2], aH[mt][3],
                                 bH[q][0], bH[q][1]);
#pragma unroll
                for (int mt = 0; mt < 2; mt++)
#pragma unroll
                    for (int q = 0; q < 2; q++)
                        MMA_BF16(acc[mt][2*p+q], aL[mt][0], aL[mt][1], aL[mt][2], aL[mt][3],
                                 bH[q][0], bH[q][1]);
#pragma unroll
                for (int mt = 0; mt < 2; mt++)
#pragma unroll
                    for (int q = 0; q < 2; q++)
                        MMA_BF16(acc[mt][2*p+q], aH[mt][0], aH[mt][1], aH[mt][2], aH[mt][3],
                                 bL[q][0], bL[q][1]);
            }
        }
        __syncthreads();
    }

    // ===== final epilogue: bias + relu, f32 out + fused BN stats =====
#pragma unroll
    for (int nt = 0; nt < 8; nt++) {
        int col = n_off + nt * 8 + tig * 2;
        float c0 = b2[col], c1 = b2[col + 1];
        float s0 = 0.f, s1 = 0.f, q0 = 0.f, q1 = 0.f;
#pragma unroll
        for (int mt = 0; mt < 2; mt++) {
            int r0 = bm * 128 + m_off + mt * 16 + gid;
            float* cc = acc[mt][nt];
            if (r0 < M) {
                float o0 = fmaxf(cc[0] + c0, 0.f);
                float o1 = fmaxf(cc[1] + c1, 0.f);
                float2 o; o.x = o0; o.y = o1;
                *(float2*)(Cf + (long long)r0 * 256 + col) = o;
                s0 += o0; s1 += o1; q0 += o0 * o0; q1 += o1 * o1;
            }
            if (r0 + 8 < M) {
                float o2 = fmaxf(cc[2] + c0, 0.f);
                float o3 = fmaxf(cc[3] + c1, 0.f);
                float2 o; o.x = o2; o.y = o3;
                *(float2*)(Cf + (long long)(r0 + 8) * 256 + col) = o;
                s0 += o2; s1 += o3; q0 += o2 * o2; q1 += o3 * o3;
            }
        }
#pragma unroll
        for (int m = 4; m < 32; m <<= 1) {
            s0 += __shfl_xor_sync(0xffffffffu, s0, m);
            s1 += __shfl_xor_sync(0xffffffffu, s1, m);
            q0 += __shfl_xor_sync(0xffffffffu, q0, m);
            q1 += __shfl_xor_sync(0xffffffffu, q1, m);
        }
        if (gid == 0) {
            atomicAdd(&g_stats[col], s0);
            atomicAdd(&g_stats[col + 1], s1);
            atomicAdd(&g_stats[DIM + col], q0);
            atomicAdd(&g_stats[DIM + col + 1], q1);
        }
    }
}

// ---------------------------------------------------------------------------
// Per-layer output: norm(m) -> outn slice + pooled sums. Block 0 publishes
// the affine for the next layer's gather.
#define ROWS_PB 128
__global__ void outpool_kernel(const float* __restrict__ m,
                               const float* __restrict__ g, const float* __restrict__ b,
                               const void* __restrict__ batch,
                               float* __restrict__ outn,
                               float* __restrict__ pooled, int layer) {
    int col = threadIdx.x;
    int is64 = g_idx64;
    float mu  = g_stats[col] * (1.f / NN);
    float var = g_stats[DIM + col] * (1.f / NN) - mu * mu;
    float sc  = g[col] * rsqrtf(var + BN_EPS);
    float sh  = b[col] - mu * sc;
    if (blockIdx.x == 0) { g_sc[col] = sc; g_sh[col] = sh; }

    int n0 = blockIdx.x * ROWS_PB;
    int n1 = min(n0 + ROWS_PB, NN);
    float acc = 0.f;
    long long cur = load_idx(batch, n0, is64);
    for (int n = n0; n < n1; n++) {
        float v = m[(long long)n * DIM + col] * sc + sh;
        outn[(long long)n * OUTD + layer * DIM + col] = v;
        long long bb = load_idx(batch, n, is64);
        if (bb != cur) {
            atomicAdd(&pooled[cur * OUTD + layer * DIM + col], acc);
            acc = 0.f;
            cur = bb;
        }
        acc += v;
    }
    atomicAdd(&pooled[cur * OUTD + layer * DIM + col], acc);
}

// ---------------------------------------------------------------------------
extern "C" void kernel_launch(void* const* d_in, const int* in_sizes, int n_in,
                              void* d_out, int out_size) {
    const float* x     = (const float*)d_in[0];
    const void*  ei    = d_in[1];
    const void*  batch = d_in[2];

    float* out    = (float*)d_out;
    float* pooled = out;                          // [NG, OUTD]
    float* outn   = out + (long long)NG * OUTD;   // [NN, OUTD]

    float *bufB;
    __nv_bfloat16 *whi, *wlo;
    uint4 *aggH, *aggL;
    cudaGetSymbolAddress((void**)&bufB, g_bufB4);
    cudaGetSymbolAddress((void**)&whi, g_whi);
    cudaGetSymbolAddress((void**)&wlo, g_wlo);
    cudaGetSymbolAddress((void**)&aggH, g_aggH4);
    cudaGetSymbolAddress((void**)&aggL, g_aggL4);

    cudaFuncSetAttribute(mlp_fused, cudaFuncAttributeMaxDynamicSharedMemorySize,
                         MLP_SMEM);

    // setup (3 launches): prep (detect+edges+weights+pooled zero), scan, fill
    prep_kernel<<<3125, 256>>>(ei,
        (const float*)d_in[3],  (const float*)d_in[5],
        (const float*)d_in[9],  (const float*)d_in[11],
        (const float*)d_in[15], (const float*)d_in[17],
        whi, wlo, pooled);
    scan_kernel<<<1, 1024>>>();
    fillcsr_kernel<<<3125, 256>>>();

    const int woffs[6] = {0, 32768, 98304, 163840, 229376, 294912};

    const float* h = x;
    for (int l = 0; l < NL; l++) {
        int F = (l == 0) ? FIN : DIM;
        const float* b1 = (const float*)d_in[3 + 6 * l + 1];
        const float* b2 = (const float*)d_in[3 + 6 * l + 3];
        const float* gg = (const float*)d_in[3 + 6 * l + 4];
        const float* bb = (const float*)d_in[3 + 6 * l + 5];

        // gather (+ prev BN affine) -> pre-split bf16 agg; zeroes stats
        gather_split<<<6250, 256>>>(h, F, l > 0,
                                    (__nv_bfloat16*)aggH, (__nv_bfloat16*)aggL);

        // fused MLP: both GEMMs in one kernel, t in SMEM, BN stats fused
        mlp_fused<<<(NN + 127) / 128, 512, MLP_SMEM>>>(
            aggH, aggL,
            whi + woffs[2*l],   wlo + woffs[2*l],   b1,
            whi + woffs[2*l+1], wlo + woffs[2*l+1], b2,
            bufB, NN, F);

        // outputs: outn slice + pooled; publish affine for next gather
        outpool_kernel<<<(NN + ROWS_PB - 1) / ROWS_PB, DIM>>>(
            bufB, gg, bb, batch, outn, pooled, l);

        h = bufB;
    }
}

// round 14
// speedup vs baseline: 1.2046x; 1.1546x over previous
#include <cuda_runtime.h>
#include <cuda_fp16.h>
#include <stdint.h>

#define NN   50000
#define NE   800000
#define FIN  128
#define DIM  256
#define NG   512
#define NL   3
#define OUTD (NL*DIM)   // 768
#define BN_EPS 1e-5f
#define MPAD 50048      // 391*128

// Scratch
__device__ float4 g_bufB4[NN*DIM/4];      // m (post-MLP, f32)
__device__ uint4  g_aggH4[MPAD*DIM*2/16]; // agg hi (fp16 [MPAD][K])
__device__ uint4  g_aggL4[MPAD*DIM*2/16]; // agg lo
__device__ float  g_stats[2*DIM];         // per-column sum, sumsq
__device__ float  g_sc[DIM], g_sh[DIM];   // published BN affine of prev layer
__device__ int    g_idx64;
// fp16 weight images, N-major ([n][k]) per (t,chunk) 128x32 tile.
__device__ __half g_whi[360448];
// CSR scratch
__device__ int g_deg[NN];
__device__ int g_rowstart[NN + 1];
__device__ int g_pos[NE];
__device__ int g_src32[NE];
__device__ int g_dst32[NE];
__device__ int g_eidx[NE];

// ---------------------------------------------------------------------------
__device__ __forceinline__ uint32_t smem_u32(const void* p) {
    uint32_t a;
    asm("{ .reg .u64 t; cvta.to.shared.u64 t, %1; cvt.u32.u64 %0, t; }" : "=r"(a) : "l"(p));
    return a;
}
__device__ __forceinline__ uint32_t pack_hf2(float a, float b) {
    uint32_t r;
    asm("cvt.rn.f16x2.f32 %0, %1, %2;" : "=r"(r) : "f"(b), "f"(a));
    return r;
}
__device__ __forceinline__ void splithf(float x, float& h, float& l) {
    __half hb = __float2half_rn(x);
    h = __half2float(hb);
    l = x - h;
}
#define LDSM_X4(r0, r1, r2, r3, addr)                                          \
    asm volatile("ldmatrix.sync.aligned.m8n8.x4.shared.b16 {%0,%1,%2,%3}, [%4];" \
                 : "=r"(r0), "=r"(r1), "=r"(r2), "=r"(r3) : "r"(addr))
#define MMA_F16(c, a0, a1, a2, a3, b0, b1)                                     \
    asm volatile(                                                              \
        "mma.sync.aligned.m16n8k16.row.col.f32.f16.f16.f32 "                   \
        "{%0,%1,%2,%3}, {%4,%5,%6,%7}, {%8,%9}, {%0,%1,%2,%3};"                \
        : "+f"(c[0]), "+f"(c[1]), "+f"(c[2]), "+f"(c[3])                       \
        : "r"(a0), "r"(a1), "r"(a2), "r"(a3), "r"(b0), "r"(b1))
#define CP_ASYNC16(dst, src)                                                   \
    asm volatile("cp.async.ca.shared.global [%0], [%1], 16;"                   \
                 :: "r"(dst), "l"(src) : "memory")
#define CP_COMMIT() asm volatile("cp.async.commit_group;" ::: "memory")

__device__ __forceinline__ long long load_idx(const void* p, long long i, int is64) {
    return is64 ? ((const long long*)p)[i] : (long long)((const int*)p)[i];
}

// ---------------------------------------------------------------------------
// prep: dtype detect, edge decode + degree histogram, fp16 weight images,
// pooled zeroing. (g_deg is re-zeroed by scan each call.)
#define WTOT 360448
__global__ void prep_kernel(const void* __restrict__ ei,
                            const float* w0, const float* w1, const float* w2,
                            const float* w3, const float* w4, const float* w5,
                            __half* __restrict__ whi,
                            float* __restrict__ pooled) {
    int stride = gridDim.x * blockDim.x;
    int gidx = blockIdx.x * blockDim.x + threadIdx.x;
    unsigned int z = 0u;
    const unsigned int* er = (const unsigned int*)ei;
#pragma unroll
    for (int k = 0; k < 8; k++) z |= er[2 * k + 1];
    int is64 = (z == 0u) ? 1 : 0;
    if (gidx == 0) g_idx64 = is64;

    if (gidx < NG * OUTD) pooled[gidx] = 0.f;

    for (int e = gidx; e < NE; e += stride) {
        int s = (int)load_idx(ei, e, is64);
        int d = (int)load_idx(ei, (long long)NE + e, is64);
        g_src32[e] = s;
        g_dst32[e] = d;
        g_pos[e] = atomicAdd(&g_deg[d], 1);
    }
    const float* ws[6] = {w0, w1, w2, w3, w4, w5};
    const int woffs[6] = {0, 32768, 98304, 163840, 229376, 294912};
    for (int idx = gidx; idx < WTOT; idx += stride) {
        int wsel, local, K;
        if (idx < 32768) { wsel = 0; local = idx; K = FIN; }
        else { wsel = 1 + ((idx - 32768) >> 16); local = (idx - 32768) & 65535; K = DIM; }
        int k = local >> 8, n = local & 255;
        int nch = K >> 5;
        int t = n >> 7, nl = n & 127, c = k >> 5, kk = k & 31;
        int off = woffs[wsel] + (t * nch + c) * 4096 + nl * 32 + kk;
        whi[off] = __float2half_rn(ws[wsel][local]);
    }
}

// Single-block scan: degrees -> rowstart (+ sentinel), then re-zero degrees.
__global__ void scan_kernel() {
    __shared__ int sm[1024];
    int t = threadIdx.x;
    const int CH = (NN + 1023) / 1024;
    int b0 = t * CH, b1 = min(b0 + CH, NN);
    int s = 0;
    for (int i = b0; i < b1; i++) s += g_deg[i];
    sm[t] = s;
    __syncthreads();
    for (int off = 1; off < 1024; off <<= 1) {
        int v = (t >= off) ? sm[t - off] : 0;
        __syncthreads();
        sm[t] += v;
        __syncthreads();
    }
    int run = (t == 0) ? 0 : sm[t - 1];
    for (int i = b0; i < b1; i++) { g_rowstart[i] = run; run += g_deg[i]; }
    if (t == 1023) g_rowstart[NN] = sm[1023];
    for (int i = b0; i < b1; i++) g_deg[i] = 0;
}

__global__ void fillcsr_kernel() {
    int stride = gridDim.x * blockDim.x;
    for (int e = blockIdx.x * blockDim.x + threadIdx.x; e < NE; e += stride)
        g_eidx[g_rowstart[g_dst32[e]] + g_pos[e]] = g_src32[e];
}

// ---------------------------------------------------------------------------
// CSR gather + (optional) prev BN affine + fp16 hi/lo split. One warp/node.
// Blocks 0-1 also zero g_stats for this layer's fused-stats GEMM.
__global__ void gather_split(const float* __restrict__ h, int F, int use_affine,
                             __half* __restrict__ oH, __half* __restrict__ oL) {
    if (blockIdx.x < 2) {
        int i = blockIdx.x * 256 + threadIdx.x;
        if (i < 2 * DIM) g_stats[i] = 0.f;
    }
    int gw = (blockIdx.x * blockDim.x + threadIdx.x) >> 5;
    if (gw >= NN) return;
    int lane = threadIdx.x & 31;
    int start = g_rowstart[gw];
    int deg = g_rowstart[gw + 1] - start;
    int F4 = F >> 2;
    bool wide = (F4 == 64);
    const float4* hv = (const float4*)h;
    const float4* hp = hv + (long long)gw * F4 + lane;
    float4 a0 = hp[0];
    float4 a1 = wide ? hp[32] : make_float4(0.f, 0.f, 0.f, 0.f);
    for (int i0 = 0; i0 < deg; i0 += 32) {
        int mye = (i0 + lane < deg) ? g_eidx[start + i0 + lane] : 0;
        int cnt = min(32, deg - i0);
        for (int j = 0; j < cnt; j++) {
            int s = __shfl_sync(0xffffffffu, mye, j);
            const float4* sp = hv + (long long)s * F4 + lane;
            float4 v = sp[0];
            a0.x += v.x; a0.y += v.y; a0.z += v.z; a0.w += v.w;
            if (wide) {
                float4 u = sp[32];
                a1.x += u.x; a1.y += u.y; a1.z += u.z; a1.w += u.w;
            }
        }
    }
    int c0 = lane * 4;
    if (use_affine) {
        float cnt = (float)(deg + 1);
        a0.x = g_sc[c0+0]*a0.x + cnt*g_sh[c0+0];
        a0.y = g_sc[c0+1]*a0.y + cnt*g_sh[c0+1];
        a0.z = g_sc[c0+2]*a0.z + cnt*g_sh[c0+2];
        a0.w = g_sc[c0+3]*a0.w + cnt*g_sh[c0+3];
        if (wide) {
            int c1 = 128 + c0;
            a1.x = g_sc[c1+0]*a1.x + cnt*g_sh[c1+0];
            a1.y = g_sc[c1+1]*a1.y + cnt*g_sh[c1+1];
            a1.z = g_sc[c1+2]*a1.z + cnt*g_sh[c1+2];
            a1.w = g_sc[c1+3]*a1.w + cnt*g_sh[c1+3];
        }
    }
    {
        float h0,l0,h1,l1,h2,l2,h3,l3;
        splithf(a0.x,h0,l0); splithf(a0.y,h1,l1); splithf(a0.z,h2,l2); splithf(a0.w,h3,l3);
        uint2 H; H.x = pack_hf2(h0,h1); H.y = pack_hf2(h2,h3);
        uint2 L; L.x = pack_hf2(l0,l1); L.y = pack_hf2(l2,l3);
        *(uint2*)(oH + (size_t)gw * F + c0) = H;
        *(uint2*)(oL + (size_t)gw * F + c0) = L;
    }
    if (wide) {
        float h0,l0,h1,l1,h2,l2,h3,l3;
        splithf(a1.x,h0,l0); splithf(a1.y,h1,l1); splithf(a1.z,h2,l2); splithf(a1.w,h3,l3);
        uint2 H; H.x = pack_hf2(h0,h1); H.y = pack_hf2(h2,h3);
        uint2 L; L.x = pack_hf2(l0,l1); L.y = pack_hf2(l2,l3);
        *(uint2*)(oH + (size_t)gw * F + 128 + c0) = H;
        *(uint2*)(oL + (size_t)gw * F + 128 + c0) = L;
    }
}

// ---------------------------------------------------------------------------
// Fused MLP: m = relu(relu(agg@W1+b1)@W2+b2), t in SMEM, 2-term fp16
// compensation (A = hi+lo fp16, W = fp16): acc = aH*b + aL*b.
// SMEM: stage = AH(10240) AL(10240) BH(20480) = 40960; two stages; then
// t hi/lo at 81920/149504 (stride 528).
#define ARS 80
#define AL_OFF 10240
#define BH_OFF 20480
#define STG1   40960
#define T_HI   81920
#define T_LO   149504
#define TSTR   528
#define MLP_SMEM 217088

__global__ void __launch_bounds__(512) mlp_fused(
    const uint4* __restrict__ AH, const uint4* __restrict__ AL,
    const __half* __restrict__ W1h, const float* __restrict__ b1,
    const __half* __restrict__ W2h, const float* __restrict__ b2,
    float* __restrict__ Cf, int M, int K1) {
    extern __shared__ __align__(16) char dsm[];
    int tid = threadIdx.x, wid = tid >> 5, lane = tid & 31;
    int bm = blockIdx.x;
    int nch1 = K1 >> 5;

    uint32_t sb = (smem_u32(dsm) + 127) & ~127u;
    int m_off = (wid & 3) * 32;
    int n_off = (wid >> 2) * 64;

    int aRowL = (lane & 7) + ((lane >> 3) & 1) * 8;
    int aColL = (lane >> 4) * 16;
    int bRowL = ((lane >> 4) * 8) + (lane & 7);
    int bColL = ((lane >> 3) & 1) * 16;
    int gid = lane >> 2, tig = lane & 3;

    float acc[2][8][4] = {};

    int rowA = tid >> 2, segA = tid & 3;
    long long aRowBase = ((long long)(bm * 128 + rowA) * K1) >> 3;
    uint32_t aDst = rowA * ARS + segA * 16;

    auto issue1 = [&](int c, uint32_t stg) {
        long long aIdx = aRowBase + c * 4 + segA;
        CP_ASYNC16(stg + aDst, AH + aIdx);
        CP_ASYNC16(stg + aDst + AL_OFF, AL + aIdx);
#pragma unroll
        for (int i = 0; i < 2; i++) {
            int p = tid + i * 512;
            int row = p >> 2, seg = p & 3;
            int t = row >> 7, nl = row & 127;
            long long srcIdx = ((long long)(t * nch1 + c) * 512) + nl * 4 + seg;
            CP_ASYNC16(stg + BH_OFF + row * ARS + seg * 16, (const uint4*)W1h + srcIdx);
        }
    };
    auto issue2 = [&](int c, uint32_t stg) {
#pragma unroll
        for (int i = 0; i < 2; i++) {
            int p = tid + i * 512;
            int row = p >> 2, seg = p & 3;
            int t = row >> 7, nl = row & 127;
            long long srcIdx = ((long long)(t * 8 + c) * 512) + nl * 4 + seg;
            CP_ASYNC16(stg + BH_OFF + row * ARS + seg * 16, (const uint4*)W2h + srcIdx);
        }
    };

    // ===== phase 1: t = relu(agg @ W1 + b1), double-buffered =====
    issue1(0, sb);
    CP_COMMIT();
    for (int c = 0; c < nch1; c++) {
        uint32_t stg = sb + (c & 1) * STG1;
        if (c + 1 < nch1) {
            issue1(c + 1, sb + ((c + 1) & 1) * STG1);
            CP_COMMIT();
            asm volatile("cp.async.wait_group 1;" ::: "memory");
        } else {
            asm volatile("cp.async.wait_group 0;" ::: "memory");
        }
        __syncthreads();
#pragma unroll
        for (int ks = 0; ks < 2; ks++) {
            uint32_t aH[2][4], aL[2][4];
#pragma unroll
            for (int mt = 0; mt < 2; mt++) {
                uint32_t ad = stg + (m_off + mt * 16 + aRowL) * ARS + ks * 32 + aColL;
                LDSM_X4(aH[mt][0], aH[mt][1], aH[mt][2], aH[mt][3], ad);
                LDSM_X4(aL[mt][0], aL[mt][1], aL[mt][2], aL[mt][3], ad + AL_OFF);
            }
#pragma unroll
            for (int p = 0; p < 4; p++) {
                uint32_t bH[2][2];
                uint32_t ad = stg + BH_OFF + (n_off + p * 16 + bRowL) * ARS + ks * 32 + bColL;
                LDSM_X4(bH[0][0], bH[0][1], bH[1][0], bH[1][1], ad);
#pragma unroll
                for (int mt = 0; mt < 2; mt++)
#pragma unroll
                    for (int q = 0; q < 2; q++)
                        MMA_F16(acc[mt][2*p+q], aH[mt][0], aH[mt][1], aH[mt][2], aH[mt][3],
                                bH[q][0], bH[q][1]);
#pragma unroll
                for (int mt = 0; mt < 2; mt++)
#pragma unroll
                    for (int q = 0; q < 2; q++)
                        MMA_F16(acc[mt][2*p+q], aL[mt][0], aL[mt][1], aL[mt][2], aL[mt][3],
                                bH[q][0], bH[q][1]);
            }
        }
        __syncthreads();
    }

    // ===== phase-1 epilogue: bias+relu+split -> t in SMEM; reset acc =====
#pragma unroll
    for (int nt = 0; nt < 8; nt++) {
        int col = n_off + nt * 8 + tig * 2;
        float c0 = b1[col], c1 = b1[col + 1];
#pragma unroll
        for (int mt = 0; mt < 2; mt++) {
            float* cc = acc[mt][nt];
            int r0 = m_off + mt * 16 + gid;
            {
                float o0 = fmaxf(cc[0] + c0, 0.f);
                float o1 = fmaxf(cc[1] + c1, 0.f);
                float h0,l0,h1,l1;
                splithf(o0,h0,l0); splithf(o1,h1,l1);
                uint32_t ad = sb + T_HI + r0 * TSTR + col * 2;
                asm volatile("st.shared.b32 [%0], %1;" :: "r"(ad), "r"(pack_hf2(h0,h1)) : "memory");
                asm volatile("st.shared.b32 [%0], %1;" :: "r"(ad + (T_LO - T_HI)), "r"(pack_hf2(l0,l1)) : "memory");
            }
            {
                float o2 = fmaxf(cc[2] + c0, 0.f);
                float o3 = fmaxf(cc[3] + c1, 0.f);
                float h2,l2,h3,l3;
                splithf(o2,h2,l2); splithf(o3,h3,l3);
                uint32_t ad = sb + T_HI + (r0 + 8) * TSTR + col * 2;
                asm volatile("st.shared.b32 [%0], %1;" :: "r"(ad), "r"(pack_hf2(h2,h3)) : "memory");
                asm volatile("st.shared.b32 [%0], %1;" :: "r"(ad + (T_LO - T_HI)), "r"(pack_hf2(l2,l3)) : "memory");
            }
            cc[0] = cc[1] = cc[2] = cc[3] = 0.f;
        }
    }
    __syncthreads();

    // ===== phase 2: m = relu(t @ W2 + b2), A from SMEM t, B double-buffered =====
    issue2(0, sb);
    CP_COMMIT();
    for (int c = 0; c < 8; c++) {
        uint32_t stg = sb + (c & 1) * STG1;
        if (c + 1 < 8) {
            issue2(c + 1, sb + ((c + 1) & 1) * STG1);
            CP_COMMIT();
            asm volatile("cp.async.wait_group 1;" ::: "memory");
        } else {
            asm volatile("cp.async.wait_group 0;" ::: "memory");
        }
        __syncthreads();
#pragma unroll
        for (int ks = 0; ks < 2; ks++) {
            uint32_t aH[2][4], aL[2][4];
#pragma unroll
            for (int mt = 0; mt < 2; mt++) {
                uint32_t ad = sb + T_HI + (m_off + mt * 16 + aRowL) * TSTR + c * 64 + ks * 32 + aColL;
                LDSM_X4(aH[mt][0], aH[mt][1], aH[mt][2], aH[mt][3], ad);
                LDSM_X4(aL[mt][0], aL[mt][1], aL[mt][2], aL[mt][3], ad + (T_LO - T_HI));
            }
#pragma unroll
            for (int p = 0; p < 4; p++) {
                uint32_t bH[2][2];
                uint32_t ad = stg + BH_OFF + (n_off + p * 16 + bRowL) * ARS + ks * 32 + bColL;
                LDSM_X4(bH[0][0], bH[0][1], bH[1][0], bH[1][1], ad);
#pragma unroll
                for (int mt = 0; mt < 2; mt++)
#pragma unroll
                    for (int q = 0; q < 2; q++)
                        MMA_F16(acc[mt][2*p+q], aH[mt][0], aH[mt][1], aH[mt][2], aH[mt][3],
                                bH[q][0], bH[q][1]);
#pragma unroll
                for (int mt = 0; mt < 2; mt++)
#pragma unroll
                    for (int q = 0; q < 2; q++)
                        MMA_F16(acc[mt][2*p+q], aL[mt][0], aL[mt][1], aL[mt][2], aL[mt][3],
                                bH[q][0], bH[q][1]);
            }
        }
        __syncthreads();
    }

    // ===== final epilogue: bias + relu, f32 out + fused BN stats =====
#pragma unroll
    for (int nt = 0; nt < 8; nt++) {
        int col = n_off + nt * 8 + tig * 2;
        float c0 = b2[col], c1 = b2[col + 1];
        float s0 = 0.f, s1 = 0.f, q0 = 0.f, q1 = 0.f;
#pragma unroll
        for (int mt = 0; mt < 2; mt++) {
            int r0 = bm * 128 + m_off + mt * 16 + gid;
            float* cc = acc[mt][nt];
            if (r0 < M) {
                float o0 = fmaxf(cc[0] + c0, 0.f);
                float o1 = fmaxf(cc[1] + c1, 0.f);
                float2 o; o.x = o0; o.y = o1;
                *(float2*)(Cf + (long long)r0 * 256 + col) = o;
                s0 += o0; s1 += o1; q0 += o0 * o0; q1 += o1 * o1;
            }
            if (r0 + 8 < M) {
                float o2 = fmaxf(cc[2] + c0, 0.f);
                float o3 = fmaxf(cc[3] + c1, 0.f);
                float2 o; o.x = o2; o.y = o3;
                *(float2*)(Cf + (long long)(r0 + 8) * 256 + col) = o;
                s0 += o2; s1 += o3; q0 += o2 * o2; q1 += o3 * o3;
            }
        }
#pragma unroll
        for (int m = 4; m < 32; m <<= 1) {
            s0 += __shfl_xor_sync(0xffffffffu, s0, m);
            s1 += __shfl_xor_sync(0xffffffffu, s1, m);
            q0 += __shfl_xor_sync(0xffffffffu, q0, m);
            q1 += __shfl_xor_sync(0xffffffffu, q1, m);
        }
        if (gid == 0) {
            atomicAdd(&g_stats[col], s0);
            atomicAdd(&g_stats[col + 1], s1);
            atomicAdd(&g_stats[DIM + col], q0);
            atomicAdd(&g_stats[DIM + col + 1], q1);
        }
    }
}

// ---------------------------------------------------------------------------
// Per-layer output: norm(m) -> outn slice + pooled sums. Block 0 publishes
// the affine for the next layer's gather.
#define ROWS_PB 128
__global__ void outpool_kernel(const float* __restrict__ m,
                               const float* __restrict__ g, const float* __restrict__ b,
                               const void* __restrict__ batch,
                               float* __restrict__ outn,
                               float* __restrict__ pooled, int layer) {
    int col = threadIdx.x;
    int is64 = g_idx64;
    float mu  = g_stats[col] * (1.f / NN);
    float var = g_stats[DIM + col] * (1.f / NN) - mu * mu;
    float sc  = g[col] * rsqrtf(var + BN_EPS);
    float sh  = b[col] - mu * sc;
    if (blockIdx.x == 0) { g_sc[col] = sc; g_sh[col] = sh; }

    int n0 = blockIdx.x * ROWS_PB;
    int n1 = min(n0 + ROWS_PB, NN);
    float acc = 0.f;
    long long cur = load_idx(batch, n0, is64);
    for (int n = n0; n < n1; n++) {
        float v = m[(long long)n * DIM + col] * sc + sh;
        outn[(long long)n * OUTD + layer * DIM + col] = v;
        long long bb = load_idx(batch, n, is64);
        if (bb != cur) {
            atomicAdd(&pooled[cur * OUTD + layer * DIM + col], acc);
            acc = 0.f;
            cur = bb;
        }
        acc += v;
    }
    atomicAdd(&pooled[cur * OUTD + layer * DIM + col], acc);
}

// ---------------------------------------------------------------------------
extern "C" void kernel_launch(void* const* d_in, const int* in_sizes, int n_in,
                              void* d_out, int out_size) {
    const float* x     = (const float*)d_in[0];
    const void*  ei    = d_in[1];
    const void*  batch = d_in[2];

    float* out    = (float*)d_out;
    float* pooled = out;                          // [NG, OUTD]
    float* outn   = out + (long long)NG * OUTD;   // [NN, OUTD]

    float *bufB;
    __half *whi;
    uint4 *aggH, *aggL;
    cudaGetSymbolAddress((void**)&bufB, g_bufB4);
    cudaGetSymbolAddress((void**)&whi, g_whi);
    cudaGetSymbolAddress((void**)&aggH, g_aggH4);
    cudaGetSymbolAddress((void**)&aggL, g_aggL4);

    cudaFuncSetAttribute(mlp_fused, cudaFuncAttributeMaxDynamicSharedMemorySize,
                         MLP_SMEM);

    // setup: prep (detect+edges+weights+pooled zero), scan, fill
    prep_kernel<<<3125, 256>>>(ei,
        (const float*)d_in[3],  (const float*)d_in[5],
        (const float*)d_in[9],  (const float*)d_in[11],
        (const float*)d_in[15], (const float*)d_in[17],
        whi, pooled);
    scan_kernel<<<1, 1024>>>();
    fillcsr_kernel<<<3125, 256>>>();

    const int woffs[6] = {0, 32768, 98304, 163840, 229376, 294912};

    const float* h = x;
    for (int l = 0; l < NL; l++) {
        int F = (l == 0) ? FIN : DIM;
        const float* b1 = (const float*)d_in[3 + 6 * l + 1];
        const float* b2 = (const float*)d_in[3 + 6 * l + 3];
        const float* gg = (const float*)d_in[3 + 6 * l + 4];
        const float* bb = (const float*)d_in[3 + 6 * l + 5];

        // gather (+ prev BN affine) -> pre-split fp16 agg; zeroes stats
        gather_split<<<6250, 256>>>(h, F, l > 0,
                                    (__half*)aggH, (__half*)aggL);

        // fused MLP: both GEMMs in one kernel, t in SMEM, 2-term fp16 comp
        mlp_fused<<<(NN + 127) / 128, 512, MLP_SMEM>>>(
            aggH, aggL,
            whi + woffs[2*l], b1,
            whi + woffs[2*l+1], b2,
            bufB, NN, F);

        // outputs: outn slice + pooled; publish affine for next gather
        outpool_kernel<<<(NN + ROWS_PB - 1) / ROWS_PB, DIM>>>(
            bufB, gg, bb, batch, outn, pooled, l);

        h = bufB;
    }
}